// round 17
// baseline (speedup 1.0000x reference)
#include <cuda_runtime.h>
#include <stdint.h>
#include <math.h>

// 1/sqrt(1 + 1e-3)
#define ISRC 0.9995003746877732f
#define XS 68                      // x row stride (floats)
#define KEXP -14.42695040888963f   // -10 * log2(e)
#define KINV (1.0f / KEXP)

typedef unsigned long long ull;

// scratch (static __device__ arrays: allocation-free)
__device__ float g_x0[64 * 32768];       // GNN output, (B, N*64) row-major
__device__ float g_part[128 * 64 * 128]; // split-K partials: (kchunk, b, d)

// ---------------- f32x2 helpers (Blackwell packed fp32) ----------------
__device__ __forceinline__ ull pk2(float a, float b) {
    ull r; asm("mov.b64 %0,{%1,%2};" : "=l"(r) : "f"(a), "f"(b)); return r;
}
__device__ __forceinline__ void up2(ull p, float& a, float& b) {
    asm("mov.b64 {%0,%1},%2;" : "=f"(a), "=f"(b) : "l"(p));
}
__device__ __forceinline__ ull add2(ull a, ull b) {
    ull r; asm("add.rn.f32x2 %0,%1,%2;" : "=l"(r) : "l"(a), "l"(b)); return r;
}
__device__ __forceinline__ ull fma2_(ull a, ull b, ull c) {
    ull r; asm("fma.rn.f32x2 %0,%1,%2,%3;" : "=l"(r) : "l"(a), "l"(b), "l"(c));
    return r;
}

// ---------------- fast math ----------------
__device__ __forceinline__ float ex2f(float x) {
    float r; asm("ex2.approx.ftz.f32 %0,%1;" : "=f"(r) : "f"(x)); return r;
}
__device__ __forceinline__ float rcpf(float x) {
    float r; asm("rcp.approx.ftz.f32 %0,%1;" : "=f"(r) : "f"(x)); return r;
}
// tanh(y) = 1 - 2/(exp(2y)+1), branchless, saturates correctly
__device__ __forceinline__ float ftanh(float y) {
    float e = ex2f(y * 2.885390081777927f);   // 2*log2(e)
    return fmaf(-2.0f, rcpf(e + 1.0f), 1.0f);
}

// ---------------- cluster / DSMEM helpers ----------------
__device__ __forceinline__ uint32_t smem_u32(const void* p) {
    uint32_t a;
    asm("{ .reg .u64 t; cvta.to.shared.u64 t, %1; cvt.u32.u64 %0, t; }"
        : "=r"(a) : "l"(p));
    return a;
}
__device__ __forceinline__ void cluster_sync_() {
    asm volatile("barrier.cluster.arrive.aligned;" ::: "memory");
    asm volatile("barrier.cluster.wait.aligned;" ::: "memory");
}
__device__ __forceinline__ uint32_t mapa_(uint32_t local, uint32_t rank) {
    uint32_t r;
    asm("mapa.shared::cluster.u32 %0, %1, %2;" : "=r"(r) : "r"(local), "r"(rank));
    return r;
}
__device__ __forceinline__ void st_cluster_f32(uint32_t addr, float v) {
    asm volatile("st.shared::cluster.f32 [%0],%1;" :: "r"(addr), "f"(v) : "memory");
}

// ---------------- pairwise S/T' — i-blocked (4 i per thread) ---------------
// thread: g = tid>>3 owns rows 4g..4g+3 (local); s = tid&7 sweeps j in
// [64s, 64s+64). f32x2 lanes hold an i-PAIR; j is scalar-broadcast into both
// lanes. After the 8-slice shfl-butterfly, every thread holds the FULL S,T
// for exactly the rows its GEMM epilogue owns (r0 = 4*(tid>>3)).
// t_ij = KEXP*d_ij = n_j + KEXP*n_i + sum_m c_j,m * (-2*KEXP*c_i,m)
template <int ND>
__device__ __forceinline__ void pairwise3(
    const float* __restrict__ cb, int tid, int h, float So[4], float To[4])
{
    const int g  = tid >> 3;
    const int s  = tid & 7;
    const int gi = h * 256 + g * 4;
    const float* cx = cb;
    const float* cy = cb + 512;
    const float* cz = cb + 1024;
    const float* cw = cb + 1536;
    const float* cn = cb + 2048;

    const float TK = -2.0f * KEXP;
    ull gx2[2], gy2[2], gz2[2], gw2[2], kni2[2];
#pragma unroll
    for (int p = 0; p < 2; p++) {
        const int i0 = gi + 2 * p, i1 = i0 + 1;
        float x0 = cx[i0], x1 = cx[i1];
        float y0 = cy[i0], y1 = cy[i1];
        float n0 = x0 * x0 + y0 * y0, n1 = x1 * x1 + y1 * y1;
        gx2[p] = pk2(TK * x0, TK * x1);
        gy2[p] = pk2(TK * y0, TK * y1);
        if (ND == 4) {
            float z0 = cz[i0], z1 = cz[i1];
            float w0 = cw[i0], w1 = cw[i1];
            n0 += z0 * z0 + w0 * w0;
            n1 += z1 * z1 + w1 * w1;
            gz2[p] = pk2(TK * z0, TK * z1);
            gw2[p] = pk2(TK * w0, TK * w1);
        } else { gz2[p] = 0ull; gw2[p] = 0ull; }
        kni2[p] = pk2(KEXP * n0, KEXP * n1);
    }

    ull S2[2] = {0ull, 0ull}, T2[2] = {0ull, 0ull};
    const int j0 = s * 64;
#pragma unroll 2
    for (int j = j0; j < j0 + 64; j += 4) {
        float xa[4], ya[4], za[4], wa[4], na[4];
        *reinterpret_cast<float4*>(xa) = *reinterpret_cast<const float4*>(cx + j);
        *reinterpret_cast<float4*>(ya) = *reinterpret_cast<const float4*>(cy + j);
        *reinterpret_cast<float4*>(na) = *reinterpret_cast<const float4*>(cn + j);
        if (ND == 4) {
            *reinterpret_cast<float4*>(za) = *reinterpret_cast<const float4*>(cz + j);
            *reinterpret_cast<float4*>(wa) = *reinterpret_cast<const float4*>(cw + j);
        }
#pragma unroll
        for (int q = 0; q < 4; q++) {
            const ull xj2 = pk2(xa[q], xa[q]);
            const ull yj2 = pk2(ya[q], ya[q]);
            const ull nj2 = pk2(na[q], na[q]);
            ull zj2 = 0ull, wj2 = 0ull;
            if (ND == 4) { zj2 = pk2(za[q], za[q]); wj2 = pk2(wa[q], wa[q]); }
#pragma unroll
            for (int p = 0; p < 2; p++) {
                ull t = add2(nj2, kni2[p]);
                t = fma2_(xj2, gx2[p], t);
                t = fma2_(yj2, gy2[p], t);
                if (ND == 4) {
                    t = fma2_(zj2, gz2[p], t);
                    t = fma2_(wj2, gw2[p], t);
                }
                float t0, t1; up2(t, t0, t1);
                ull w2 = pk2(ex2f(t0), ex2f(t1));
                S2[p] = add2(S2[p], w2);
                T2[p] = fma2_(t, w2, T2[p]);
            }
        }
    }
    // butterfly over the 8 j-slices (lanes differing in bits 0..2)
#pragma unroll
    for (int msk = 1; msk <= 4; msk <<= 1) {
#pragma unroll
        for (int p = 0; p < 2; p++) {
            S2[p] = add2(S2[p], __shfl_xor_sync(0xffffffffu, S2[p], msk));
            T2[p] = add2(T2[p], __shfl_xor_sync(0xffffffffu, T2[p], msk));
        }
    }
    up2(S2[0], So[0], So[1]); up2(S2[1], So[2], So[3]);
    up2(T2[0], To[0], To[1]); up2(T2[1], To[2], To[3]);
}

// ---------------- GEMM accumulation only (no epilogue) ---------------------
template <int FP>
__device__ __forceinline__ void gemm_accum(
    const float* x_s, const float* A_s, int tid, ull u[4][4], ull v[4][4])
{
    const int cs0 = (tid & 7) * 8;
    const int r0  = (tid >> 3) * 4;
#pragma unroll
    for (int r = 0; r < 4; r++)
#pragma unroll
        for (int c = 0; c < 4; c++) { u[r][c] = 0ull; v[r][c] = 0ull; }

    const float* xb = x_s + r0 * XS;
#pragma unroll 2
    for (int kq = 0; kq < FP / 4; kq++) {
        float xq[4][4];
#pragma unroll
        for (int r = 0; r < 4; r++)
            *reinterpret_cast<float4*>(xq[r]) =
                *reinterpret_cast<const float4*>(xb + r * XS + kq * 4);
#pragma unroll
        for (int j = 0; j < 4; j++) {
            const int k = kq * 4 + j;
            ulonglong2 a01 = *reinterpret_cast<const ulonglong2*>(&A_s[k * 64 + cs0]);
            ulonglong2 a23 = *reinterpret_cast<const ulonglong2*>(&A_s[k * 64 + cs0 + 4]);
            ulonglong2 q01 = *reinterpret_cast<const ulonglong2*>(&A_s[(FP + k) * 64 + cs0]);
            ulonglong2 q23 = *reinterpret_cast<const ulonglong2*>(&A_s[(FP + k) * 64 + cs0 + 4]);
#pragma unroll
            for (int r = 0; r < 4; r++) {
                ull xp = pk2(xq[r][j], xq[r][j]);
                u[r][0] = fma2_(xp, a01.x, u[r][0]);
                u[r][1] = fma2_(xp, a01.y, u[r][1]);
                u[r][2] = fma2_(xp, a23.x, u[r][2]);
                u[r][3] = fma2_(xp, a23.y, u[r][3]);
                v[r][0] = fma2_(xp, q01.x, v[r][0]);
                v[r][1] = fma2_(xp, q01.y, v[r][1]);
                v[r][2] = fma2_(xp, q23.x, v[r][2]);
                v[r][3] = fma2_(xp, q23.y, v[r][3]);
            }
        }
    }
}

// ---------------- epilogue: combine u/v with register s,t ------------------
template <int FP>
__device__ __forceinline__ void epilogue(
    const float* A_s, const float Sr[4], const float Tr[4],
    const float* m_s, const float* cn, int tid,
    ull u[4][4], ull v[4][4], float o[4][8])
{
    const int cs0 = (tid & 7) * 8;
    const int r0  = (tid >> 3) * 4;
#pragma unroll
    for (int r = 0; r < 4; r++) {
        const int i = r0 + r;
        const float m = m_s[i];
        const float s = fmaf(m, Sr[r], -1.f);
        const float t = Tr[r] * (m * KINV);
        const ull s2 = pk2(s, s);
#pragma unroll
        for (int c2 = 0; c2 < 4; c2++) {
            ull y2 = fma2_(s2, v[r][c2], u[r][c2]);
            float yl, yh; up2(y2, yl, yh);
            const int c = cs0 + c2 * 2;
            float a0 = (fmaf(t, A_s[2 * FP * 64 + c],     yl) + cn[c])     * m;
            float a1 = (fmaf(t, A_s[2 * FP * 64 + c + 1], yh) + cn[c + 1]) * m;
            o[r][c2 * 2]     = ftanh(fmaf(cn[64 + c],     a0, cn[128 + c]));
            o[r][c2 * 2 + 1] = ftanh(fmaf(cn[64 + c + 1], a1, cn[128 + c + 1]));
        }
    }
}

// ----------------------------------------------------------------------------
// Fused GNN, cluster of 2 CTAs per batch. Per layer:
//   pairwise (i-blocked, shfl-reduced) -> STS(A prefetch) -> GEMM-accum ->
//   syncthreads -> epilogue (+c push local & peer) -> x writeback -> cluster_sync
// ----------------------------------------------------------------------------
__global__ __launch_bounds__(512, 1) __cluster_dims__(2, 1, 1)
void gnn_fused_kernel(
    const float* __restrict__ xx,
    const float* __restrict__ e1, const float* __restrict__ e2,
    const float* __restrict__ e3,
    const float* __restrict__ A0, const float* __restrict__ b0,
    const float* __restrict__ Ar, const float* __restrict__ br,
    const float* __restrict__ bng, const float* __restrict__ bnb)
{
    extern __shared__ float sm[];
    float* cbuf   = sm;                   // 2 blocks x 5 arrays x 512 = 5120
    float* x_s    = cbuf + 5120;          // 256*XS = 17408
    float* A_s    = x_s + 256 * XS;       // 2 x 8256 = 16512
    float* m_s    = A_s + 16512;          // 256
    float* cn_all = m_s + 256;            // 5*192 = 960

    const int h   = blockIdx.x;           // rank in cluster (row half)
    const int ph  = 1 - h;
    const int b   = blockIdx.y;
    const int tid = threadIdx.x;
    const int cs0 = (tid & 7) * 8;
    const int r0  = (tid >> 3) * 4;
    const bool pusher = (cs0 == 56);      // owns output cols 56..63

    // ---- init: mask, layer-0 features (FP=36), c block0, A0 buf0, cn_all ---
    if (tid < 256) {
        const float* r = xx + ((size_t)b * 512 + h * 256 + tid) * 30;
        m_s[tid] = r[0];
        int i1 = (int)fabsf(r[27]);
        int i2 = (int)fabsf(r[28]);
        int i3 = (int)fabsf(r[29]);
        float* xr = x_s + tid * XS;
        xr[0] = e1[2 * i1]; xr[1] = e1[2 * i1 + 1];
        xr[2] = e2[2 * i2]; xr[3] = e2[2 * i2 + 1];
        xr[4] = e3[2 * i3]; xr[5] = e3[2 * i3 + 1];
#pragma unroll
        for (int k = 0; k < 27; k++) xr[6 + k] = r[k];
        xr[33] = 0.f; xr[34] = 0.f; xr[35] = 0.f;
    }
    {   // layer-0 c (ND=2) + norms for ALL 512 rows straight from xx
        const float* row = xx + ((size_t)b * 512 + tid) * 30;
        float vx = row[25], vy = row[26];
        cbuf[tid]        = vx;
        cbuf[512 + tid]  = vy;
        cbuf[2048 + tid] = KEXP * (vx * vx + vy * vy);
    }
    // stage A0 padded to FP=36 into A buffer 0
    for (int idx = tid; idx < 73 * 64; idx += 512) {
        int kp = idx >> 6, c = idx & 63;
        float val = 0.f;
        if (kp < 33)                  val = A0[kp * 64 + c];
        else if (kp >= 36 && kp < 69) val = A0[(kp - 3) * 64 + c];
        else if (kp == 72)            val = A0[66 * 64 + c];
        A_s[idx] = val;
    }
    // prestage all per-layer constants
    for (int idx = tid; idx < 960; idx += 512) {
        int l = idx / 192, r = idx - l * 192;
        float val;
        if (r < 64)        val = (l == 0) ? b0[r] : br[(l - 1) * 64 + r];
        else if (r < 128)  val = bng[l * 64 + (r - 64)] * ISRC;
        else               val = bnb[l * 64 + (r - 128)];
        cn_all[idx] = val;
    }
    __syncthreads();

    // ---- layers 0..4 ----
#pragma unroll 1
    for (int l = 0; l < 5; l++) {
        const float* Abuf = A_s + (l & 1) * 8256;
        float* Anext      = A_s + ((l + 1) & 1) * 8256;
        const float* cbR  = cbuf + (l & 1) * 2560;
        float* cbW        = cbuf + ((l + 1) & 1) * 2560;
        const float* cn   = cn_all + l * 192;

        // prefetch next layer's A (LDG now; STS after pairwise, before GEMM —
        // Anext's last readers finished before the previous layer's barrier)
        float4 pf[5]; int npf = 0;
        if (l < 4) {
            const float* A = Ar + l * 8256;
            for (int idx = tid; idx < 2064; idx += 512)
                pf[npf++] = reinterpret_cast<const float4*>(A)[idx];
        }

        float Sr[4], Tr[4];
        if (l == 0) pairwise3<2>(cbR, tid, h, Sr, Tr);
        else        pairwise3<4>(cbR, tid, h, Sr, Tr);

        if (l < 4) {
            int n = 0;
            for (int idx = tid; idx < 2064; idx += 512)
                reinterpret_cast<float4*>(Anext)[idx] = pf[n++];
        }

        ull u[4][4], v[4][4];
        if (l == 0) gemm_accum<36>(x_s, Abuf, tid, u, v);
        else        gemm_accum<64>(x_s, Abuf, tid, u, v);

        __syncthreads();   // all x_s & Abuf reads of this layer done

        float o[4][8];
        if (l == 0) epilogue<36>(Abuf, Sr, Tr, m_s, cn, tid, u, v, o);
        else        epilogue<64>(Abuf, Sr, Tr, m_s, cn, tid, u, v, o);

        if (l < 4) {
            if (pusher) {
                uint32_t lb = smem_u32(cbW);
                uint32_t pb = mapa_(lb, (uint32_t)ph);
#pragma unroll
                for (int r = 0; r < 4; r++) {
                    int gi = h * 256 + r0 + r;
                    float vx = o[r][4], vy = o[r][5], vz = o[r][6], vw = o[r][7];
                    float nj = KEXP * (vx * vx + vy * vy + vz * vz + vw * vw);
                    cbW[gi]        = vx;  cbW[512 + gi]  = vy;
                    cbW[1024 + gi] = vz;  cbW[1536 + gi] = vw;
                    cbW[2048 + gi] = nj;
                    uint32_t off = (uint32_t)gi * 4u;
                    st_cluster_f32(pb + off,          vx);
                    st_cluster_f32(pb + 2048u + off,  vy);
                    st_cluster_f32(pb + 4096u + off,  vz);
                    st_cluster_f32(pb + 6144u + off,  vw);
                    st_cluster_f32(pb + 8192u + off,  nj);
                }
            }
            // writeback x (own rows; all reads of x_s completed at the sync)
#pragma unroll
            for (int r = 0; r < 4; r++) {
                float4* dst = reinterpret_cast<float4*>(x_s + (r0 + r) * XS + cs0);
                dst[0] = make_float4(o[r][0], o[r][1], o[r][2], o[r][3]);
                dst[1] = make_float4(o[r][4], o[r][5], o[r][6], o[r][7]);
            }
            cluster_sync_();   // orders c pushes (both CTAs) + x writeback
        } else {
            // last layer: write straight to global for the dense head
#pragma unroll
            for (int r = 0; r < 4; r++) {
                float4* dst = reinterpret_cast<float4*>(
                    g_x0 + (size_t)b * 32768 + (h * 256 + r0 + r) * 64 + cs0);
                dst[0] = make_float4(o[r][0], o[r][1], o[r][2], o[r][3]);
                dst[1] = make_float4(o[r][4], o[r][5], o[r][6], o[r][7]);
            }
        }
    }
}

// ----------------------------------------------------------------------------
// Dense layer 0 split-K: 128 CTAs, each owns a K-chunk of 256. f32x2 packed.
// ----------------------------------------------------------------------------
#define D0XS 257
__global__ __launch_bounds__(256, 1) void dense0_kernel(const float* __restrict__ W)
{
    extern __shared__ float sm[];
    float* Xs = sm;                 // 64 x 257 (padded)
    float* Ws = Xs + 64 * D0XS;     // 256 x 128
    const int tid = threadIdx.x;
    const int kc  = blockIdx.x;

    for (int idx = tid; idx < 64 * 256; idx += 256) {
        int bb = idx >> 8, k = idx & 255;
        Xs[bb * D0XS + k] = g_x0[(size_t)bb * 32768 + kc * 256 + k];
    }
    const float* wsrc = W + (size_t)kc * 256 * 128;
    for (int idx = tid; idx < 256 * 128 / 4; idx += 256)
        reinterpret_cast<float4*>(Ws)[idx] =
            reinterpret_cast<const float4*>(wsrc)[idx];
    __syncthreads();

    const int rg = tid >> 4;   // 0..15 -> rows rg*4..rg*4+3
    const int cg = tid & 15;   // 0..15 -> cols cg*8..cg*8+7
    ull acc[4][4];
#pragma unroll
    for (int r = 0; r < 4; r++)
#pragma unroll
        for (int c = 0; c < 4; c++) acc[r][c] = 0ull;

#pragma unroll 2
    for (int k = 0; k < 256; k++) {
        ulonglong2 w01 = *reinterpret_cast<const ulonglong2*>(&Ws[k * 128 + cg * 8]);
        ulonglong2 w23 = *reinterpret_cast<const ulonglong2*>(&Ws[k * 128 + cg * 8 + 4]);
#pragma unroll
        for (int r = 0; r < 4; r++) {
            float xv = Xs[(rg * 4 + r) * D0XS + k];
            ull xp = pk2(xv, xv);
            acc[r][0] = fma2_(xp, w01.x, acc[r][0]);
            acc[r][1] = fma2_(xp, w01.y, acc[r][1]);
            acc[r][2] = fma2_(xp, w23.x, acc[r][2]);
            acc[r][3] = fma2_(xp, w23.y, acc[r][3]);
        }
    }
    float* dst = g_part + (size_t)kc * 8192;
#pragma unroll
    for (int r = 0; r < 4; r++) {
        ulonglong2* d = reinterpret_cast<ulonglong2*>(&dst[(rg * 4 + r) * 128 + cg * 8]);
        d[0] = make_ulonglong2(acc[r][0], acc[r][1]);
        d[1] = make_ulonglong2(acc[r][2], acc[r][3]);
    }
}

// ----------------------------------------------------------------------------
// Finalize: reduce partials, BN+sigmoid, dense1, BN+sigmoid, W2, write (64,4)
// ----------------------------------------------------------------------------
__global__ __launch_bounds__(128, 1) void finalize_kernel(
    const float* __restrict__ db0, const float* __restrict__ dW1,
    const float* __restrict__ db1, const float* __restrict__ dbng,
    const float* __restrict__ dbnb, const float* __restrict__ W2,
    const float* __restrict__ b2, float* __restrict__ out)
{
    __shared__ float h0[128];
    __shared__ float h1[128];
    const int b = blockIdx.x;
    const int d = threadIdx.x;

    float a = db0[d];
#pragma unroll 4
    for (int kc = 0; kc < 128; kc++) a += g_part[(size_t)kc * 8192 + b * 128 + d];
    a = fmaf(dbng[d] * ISRC, a, dbnb[d]);
    h0[d] = 1.f / (1.f + __expf(-a));
    __syncthreads();

    float s = 0.f;
#pragma unroll 8
    for (int k = 0; k < 128; k++) s = fmaf(h0[k], dW1[k * 128 + d], s);
    s += db1[d];
    s = fmaf(dbng[128 + d] * ISRC, s, dbnb[128 + d]);
    h1[d] = 1.f / (1.f + __expf(-s));
    __syncthreads();

    if (d < 4) {
        float o = 0.f;
        if (d < 2) {
            o = b2[d];
            for (int k = 0; k < 128; k++) o = fmaf(h1[k], W2[k * 2 + d], o);
        }
        out[b * 4 + d] = o;
    }
}

// ----------------------------------------------------------------------------
extern "C" void kernel_launch(void* const* d_in, const int* in_sizes, int n_in,
                              void* d_out, int out_size)
{
    const float* xx   = (const float*)d_in[0];
    const float* emb1 = (const float*)d_in[1];
    const float* emb2 = (const float*)d_in[2];
    const float* emb3 = (const float*)d_in[3];
    const float* A0   = (const float*)d_in[4];
    const float* b0   = (const float*)d_in[5];
    const float* Ar   = (const float*)d_in[6];
    const float* br   = (const float*)d_in[7];
    const float* bng  = (const float*)d_in[8];
    const float* bnb  = (const float*)d_in[9];
    const float* dW0  = (const float*)d_in[10];
    const float* db0  = (const float*)d_in[11];
    const float* dW1  = (const float*)d_in[12];
    const float* db1  = (const float*)d_in[13];
    const float* dbng = (const float*)d_in[14];
    const float* dbnb = (const float*)d_in[15];
    const float* W2   = (const float*)d_in[16];
    const float* b2   = (const float*)d_in[17];
    float* out = (float*)d_out;

    // 5120 + 17408 + 16512 + 256 + 960 = 40256 floats
    const int G_SMEM  = 40256 * 4;
    const int D0_SMEM = (64 * D0XS + 256 * 128) * 4;

    cudaFuncSetAttribute(gnn_fused_kernel,
                         cudaFuncAttributeMaxDynamicSharedMemorySize, G_SMEM);
    cudaFuncSetAttribute(dense0_kernel,
                         cudaFuncAttributeMaxDynamicSharedMemorySize, D0_SMEM);

    dim3 grid(2, 64);
    gnn_fused_kernel<<<grid, 512, G_SMEM>>>(
        xx, emb1, emb2, emb3, A0, b0, Ar, br, bng, bnb);
    dense0_kernel<<<128, 256, D0_SMEM>>>(dW0);
    finalize_kernel<<<64, 128>>>(db0, dW1, db1, dbng, dbnb, W2, b2, out);
}